// round 1
// baseline (speedup 1.0000x reference)
#include <cuda_runtime.h>
#include <cuda_bf16.h>
#include <math.h>

// Problem constants
#define BATCH   64
#define NF      256
#define WIN     128
#define EMB     128
#define TOPK    32
#define ALPHA   0.2f

// Scratch: Wx = x_n @ W_n + b_n, shape [BATCH*NF, EMB] fp32 (8.4 MB)
__device__ float g_Wx[BATCH * NF * EMB];

__device__ __forceinline__ float lrelu(float v) {
    return v >= 0.0f ? v : ALPHA * v;
}

// ---------------------------------------------------------------------------
// Kernel 1: GEMM  Wx[r][e] = sum_w x[r][w] * W[w][e] + b[e]
// M = BATCH*NF = 16384, K = 128, N = 128. Tile: 64 rows x 128 cols, TK=32.
// 256 threads, micro-tile 4x8 per thread (strided layout: m = ty+16i, e = tx+16j)
// ---------------------------------------------------------------------------
__global__ __launch_bounds__(256) void gemm_wx_kernel(
    const float* __restrict__ x,   // [BATCH*NF, WIN]
    const float* __restrict__ Wn,  // [WIN, EMB]
    const float* __restrict__ bn)  // [EMB]
{
    __shared__ float sX[32][65];    // [k][m], padded to kill bank conflicts
    __shared__ float sW[32][128];   // [k][e]

    const int t    = threadIdx.x;
    const int row0 = blockIdx.x * 64;
    const int tx   = t & 15;       // e-direction
    const int ty   = t >> 4;       // m-direction

    float acc[4][8];
#pragma unroll
    for (int i = 0; i < 4; i++)
#pragma unroll
        for (int j = 0; j < 8; j++) acc[i][j] = 0.0f;

    for (int kt = 0; kt < WIN; kt += 32) {
        // Load X tile (64x32), transposed into sX[k][m]
#pragma unroll
        for (int i = 0; i < 8; i++) {
            int idx = t + i * 256;
            int m = idx >> 5, w = idx & 31;
            sX[w][m] = x[(size_t)(row0 + m) * WIN + kt + w];
        }
        // Load W tile (32x128)
#pragma unroll
        for (int i = 0; i < 16; i++) {
            int idx = t + i * 256;
            int kk = idx >> 7, e = idx & 127;
            sW[kk][e] = Wn[(size_t)(kt + kk) * EMB + e];
        }
        __syncthreads();

#pragma unroll
        for (int kk = 0; kk < 32; kk++) {
            float ra[4], rb[8];
#pragma unroll
            for (int i = 0; i < 4; i++) ra[i] = sX[kk][ty + 16 * i];
#pragma unroll
            for (int j = 0; j < 8; j++) rb[j] = sW[kk][tx + 16 * j];
#pragma unroll
            for (int i = 0; i < 4; i++)
#pragma unroll
                for (int j = 0; j < 8; j++)
                    acc[i][j] = fmaf(ra[i], rb[j], acc[i][j]);
        }
        __syncthreads();
    }

    // Epilogue: add bias, store
#pragma unroll
    for (int i = 0; i < 4; i++) {
        int m = row0 + ty + 16 * i;
#pragma unroll
        for (int j = 0; j < 8; j++) {
            int e = tx + 16 * j;
            g_Wx[(size_t)m * EMB + e] = acc[i][j] + bn[e];
        }
    }
}

// ---------------------------------------------------------------------------
// Kernel 2: fused attention + output. One block per (b, n).
//   - stage 32 neighbor rows of Wx in smem (16 KB)
//   - scores:  k<16  : lrelu(dot(Wx[b,n], a1+a2))
//              k>=16 : lrelu(dot(alt[2k-32], a1) + dot(alt[2k-31], a2))
//   - + nan_to_num(bias), softmax over 32
//   - out[b,n,k,:] = att[k] * lrelu(alt[k])   (att>0 so lrelu commutes)
// ---------------------------------------------------------------------------
__global__ __launch_bounds__(256) void attn_out_kernel(
    const int*   __restrict__ edge,   // [2, NF*TOPK] (use row 0)
    const float* __restrict__ a,      // [2*EMB]
    const float* __restrict__ bias,   // [NF, TOPK]
    float*       __restrict__ out)    // [BATCH, NF, TOPK, EMB]
{
    __shared__ float sAlt[TOPK * EMB];   // 16 KB
    __shared__ int   sNbr[TOPK];
    __shared__ float sD[TOPK];
    __shared__ float sBase;
    __shared__ float sAtt[TOPK];

    const int n = blockIdx.x;
    const int b = blockIdx.y;
    const int t = threadIdx.x;

    if (t < TOPK) sNbr[t] = edge[n * TOPK + t];
    __syncthreads();

    const float* wxb = g_Wx + (size_t)b * NF * EMB;

    // Phase 1: gather 32 neighbor rows into smem (float4 vectorized)
    float4* sAlt4 = (float4*)sAlt;
#pragma unroll
    for (int i = 0; i < 4; i++) {
        int idx4 = t + i * 256;          // 0..1023
        int k  = idx4 >> 5;              // row (32 float4 per row)
        int c4 = idx4 & 31;
        const float4* src = (const float4*)(wxb + (size_t)sNbr[k] * EMB);
        sAlt4[idx4] = src[c4];
    }
    __syncthreads();

    // Phase 2: dot products. Warp w handles rows 4w..4w+3.
    const int w = t >> 5, l = t & 31;
#pragma unroll
    for (int r = 0; r < 4; r++) {
        int row = w * 4 + r;
        const float4* av = (const float4*)(a + ((row & 1) ? EMB : 0));
        float4 xv = ((const float4*)sAlt)[row * 32 + l];
        float4 av4 = av[l];
        float p = xv.x * av4.x + xv.y * av4.y + xv.z * av4.z + xv.w * av4.w;
#pragma unroll
        for (int o = 16; o > 0; o >>= 1) p += __shfl_xor_sync(0xffffffffu, p, o);
        if (l == 0) sD[row] = p;
    }
    if (w == 0) {
        const float4* rown = (const float4*)(wxb + (size_t)n * EMB);
        float4 xv  = rown[l];
        float4 a1v = ((const float4*)a)[l];
        float4 a2v = ((const float4*)(a + EMB))[l];
        float p = xv.x * (a1v.x + a2v.x) + xv.y * (a1v.y + a2v.y)
                + xv.z * (a1v.z + a2v.z) + xv.w * (a1v.w + a2v.w);
#pragma unroll
        for (int o = 16; o > 0; o >>= 1) p += __shfl_xor_sync(0xffffffffu, p, o);
        if (l == 0) sBase = p;
    }
    __syncthreads();

    // Phase 3: scores + softmax over 32 (warp 0)
    if (t < TOPK) {
        int k = t;
        float v;
        if (k < 16) v = lrelu(sBase);
        else        v = lrelu(sD[2 * k - 32] + sD[2 * k - 31]);
        float bv = bias[n * TOPK + k];
        // nan_to_num
        if (isnan(bv)) bv = 0.0f;
        else if (isinf(bv)) bv = bv > 0.0f ? 3.4028235e38f : -3.4028235e38f;
        v += bv;
        float m = v;
#pragma unroll
        for (int o = 16; o > 0; o >>= 1) m = fmaxf(m, __shfl_xor_sync(0xffffffffu, m, o));
        float ex = __expf(v - m);
        float s = ex;
#pragma unroll
        for (int o = 16; o > 0; o >>= 1) s += __shfl_xor_sync(0xffffffffu, s, o);
        sAtt[k] = ex / s;
    }
    __syncthreads();

    // Phase 4: write output, float4 stores
    float4* outp = (float4*)(out + ((size_t)(b * NF + n)) * TOPK * EMB);
#pragma unroll
    for (int i = 0; i < 4; i++) {
        int idx4 = t + i * 256;
        int k = idx4 >> 5;
        float att = sAtt[k];
        float4 v = sAlt4[idx4];
        v.x = lrelu(v.x) * att;
        v.y = lrelu(v.y) * att;
        v.z = lrelu(v.z) * att;
        v.w = lrelu(v.w) * att;
        outp[idx4] = v;
    }
}

// ---------------------------------------------------------------------------
// Launch
// Inputs (metadata order): 0:x_n 1:x_e 2:edge_indices 3:all_embeddings
//                          4:W_n  5:b_n 6:a  7:bias_n        (x_e, emb unused)
// ---------------------------------------------------------------------------
extern "C" void kernel_launch(void* const* d_in, const int* in_sizes, int n_in,
                              void* d_out, int out_size) {
    const float* x_n  = (const float*)d_in[0];
    const int*   edge = (const int*)  d_in[2];
    const float* W_n  = (const float*)d_in[4];
    const float* b_n  = (const float*)d_in[5];
    const float* a    = (const float*)d_in[6];
    const float* bias = (const float*)d_in[7];
    float* out = (float*)d_out;

    gemm_wx_kernel<<<(BATCH * NF) / 64, 256>>>(x_n, W_n, b_n);
    dim3 grid(NF, BATCH);
    attn_out_kernel<<<grid, 256>>>(edge, a, bias, out);
}

// round 2
// speedup vs baseline: 1.7211x; 1.7211x over previous
#include <cuda_runtime.h>
#include <cuda_bf16.h>
#include <math.h>

// Problem constants
#define BATCH   64
#define NF      256
#define WIN     128
#define EMB     128
#define TOPK    32
#define ALPHA   0.2f

// Scratch
__device__ float g_Wx[BATCH * NF * EMB];   // Wx = x_n @ W_n + b_n  (8.4 MB)
__device__ float g_d1[BATCH * NF];         // dot(Wx[b,r], a[:128])
__device__ float g_d2[BATCH * NF];         // dot(Wx[b,r], a[128:])

__device__ __forceinline__ float lrelu(float v) {
    return v >= 0.0f ? v : ALPHA * v;
}

// ---------------------------------------------------------------------------
// Kernel 1: GEMM  Wx[r][e] = sum_w x[r][w] * W[w][e] + b[e]
// plus fused epilogue: d1[r] = Wx[r]·a1, d2[r] = Wx[r]·a2.
// M = 16384, K = 128, N = 128. 64-row x 128-col tiles, 256 thr, 4x8 microtile.
// ---------------------------------------------------------------------------
__global__ __launch_bounds__(256) void gemm_wx_kernel(
    const float* __restrict__ x,   // [BATCH*NF, WIN]
    const float* __restrict__ Wn,  // [WIN, EMB]
    const float* __restrict__ bn,  // [EMB]
    const float* __restrict__ a)   // [2*EMB]
{
    __shared__ float sX[32][65];    // [k][m], padded
    __shared__ float sW[32][128];   // [k][e]

    const int t    = threadIdx.x;
    const int row0 = blockIdx.x * 64;
    const int tx   = t & 15;       // e-direction
    const int ty   = t >> 4;       // m-direction

    float acc[4][8];
#pragma unroll
    for (int i = 0; i < 4; i++)
#pragma unroll
        for (int j = 0; j < 8; j++) acc[i][j] = 0.0f;

    for (int kt = 0; kt < WIN; kt += 32) {
#pragma unroll
        for (int i = 0; i < 8; i++) {
            int idx = t + i * 256;
            int m = idx >> 5, w = idx & 31;
            sX[w][m] = x[(size_t)(row0 + m) * WIN + kt + w];
        }
#pragma unroll
        for (int i = 0; i < 16; i++) {
            int idx = t + i * 256;
            int kk = idx >> 7, e = idx & 127;
            sW[kk][e] = Wn[(size_t)(kt + kk) * EMB + e];
        }
        __syncthreads();

#pragma unroll
        for (int kk = 0; kk < 32; kk++) {
            float ra[4], rb[8];
#pragma unroll
            for (int i = 0; i < 4; i++) ra[i] = sX[kk][ty + 16 * i];
#pragma unroll
            for (int j = 0; j < 8; j++) rb[j] = sW[kk][tx + 16 * j];
#pragma unroll
            for (int i = 0; i < 4; i++)
#pragma unroll
                for (int j = 0; j < 8; j++)
                    acc[i][j] = fmaf(ra[i], rb[j], acc[i][j]);
        }
        __syncthreads();
    }

    // Epilogue: bias, store Wx, and fused projections d1/d2
    float a1v[8], a2v[8], bnv[8];
#pragma unroll
    for (int j = 0; j < 8; j++) {
        int e = tx + 16 * j;
        a1v[j] = __ldg(a + e);
        a2v[j] = __ldg(a + EMB + e);
        bnv[j] = __ldg(bn + e);
    }
    float p1[4] = {0, 0, 0, 0};
    float p2[4] = {0, 0, 0, 0};
#pragma unroll
    for (int i = 0; i < 4; i++) {
        int m = row0 + ty + 16 * i;
#pragma unroll
        for (int j = 0; j < 8; j++) {
            int e = tx + 16 * j;
            float val = acc[i][j] + bnv[j];
            g_Wx[(size_t)m * EMB + e] = val;
            p1[i] = fmaf(val, a1v[j], p1[i]);
            p2[i] = fmaf(val, a2v[j], p2[i]);
        }
    }
    // Reduce across the 16 tx lanes (lanes l and l^{1,2,4,8} share ty)
#pragma unroll
    for (int i = 0; i < 4; i++) {
#pragma unroll
        for (int o = 8; o > 0; o >>= 1) {
            p1[i] += __shfl_xor_sync(0xffffffffu, p1[i], o);
            p2[i] += __shfl_xor_sync(0xffffffffu, p2[i], o);
        }
    }
    if (tx == 0) {
#pragma unroll
        for (int i = 0; i < 4; i++) {
            int m = row0 + ty + 16 * i;
            g_d1[m] = p1[i];
            g_d2[m] = p2[i];
        }
    }
}

// ---------------------------------------------------------------------------
// Kernel 2: warp-autonomous attention + streaming output. One warp per (b,n).
// No shared memory, no __syncthreads.
//   lane k: score_k = lrelu( k<16 ? d1[b,n]+d2[b,n]
//                                 : d1[b,nbr[n,2k-32]] + d2[b,nbr[n,2k-31]] )
//           + nan_to_num(bias[n,k]); warp softmax -> att_k
//   then 32 rows: out[b,n,k,:] = att_k * lrelu(Wx[b, nbr[n,k]])
// ---------------------------------------------------------------------------
__global__ __launch_bounds__(256) void attn_stream_kernel(
    const int*   __restrict__ edge,   // [2, NF*TOPK] (row 0 used)
    const float* __restrict__ bias,   // [NF, TOPK]
    float*       __restrict__ out)    // [BATCH, NF, TOPK, EMB]
{
    const int gw = (blockIdx.x * blockDim.x + threadIdx.x) >> 5;  // 0..BATCH*NF-1
    const int l  = threadIdx.x & 31;
    const int b  = gw >> 8;           // NF = 256
    const int n  = gw & 255;

    const float* d1 = g_d1 + b * NF;
    const float* d2 = g_d2 + b * NF;

    // Per-lane neighbor for the OUTPUT row (nbr[n,l])
    const int nbr_l = __ldg(edge + n * TOPK + l);

    // Score for lane l
    float score;
    if (l < 16) {
        score = lrelu(d1[n] + d2[n]);
    } else {
        int j0 = 2 * l - 32;
        int n0 = __ldg(edge + n * TOPK + j0);
        int n1 = __ldg(edge + n * TOPK + j0 + 1);
        score = lrelu(d1[n0] + d2[n1]);
    }
    float bv = __ldg(bias + n * TOPK + l);
    if (isnan(bv)) bv = 0.0f;
    else if (isinf(bv)) bv = bv > 0.0f ? 3.4028235e38f : -3.4028235e38f;
    score += bv;

    // Warp softmax over 32 lanes
    float m = score;
#pragma unroll
    for (int o = 16; o > 0; o >>= 1) m = fmaxf(m, __shfl_xor_sync(0xffffffffu, m, o));
    float ex = __expf(score - m);
    float s = ex;
#pragma unroll
    for (int o = 16; o > 0; o >>= 1) s += __shfl_xor_sync(0xffffffffu, s, o);
    const float att = ex / s;

    // Streaming output: 32 rows x 32 float4 (lane = float4 index within row)
    const float* wxb = g_Wx + (size_t)b * NF * EMB;
    float4* outp = (float4*)(out + (size_t)gw * TOPK * EMB);

#pragma unroll 8
    for (int k = 0; k < TOPK; k++) {
        int   nb = __shfl_sync(0xffffffffu, nbr_l, k);
        float ak = __shfl_sync(0xffffffffu, att,   k);
        const float4* src = (const float4*)(wxb + (size_t)nb * EMB);
        float4 v = __ldg(src + l);
        v.x = lrelu(v.x) * ak;
        v.y = lrelu(v.y) * ak;
        v.z = lrelu(v.z) * ak;
        v.w = lrelu(v.w) * ak;
        __stcs(outp + k * 32 + l, v);
    }
}

// ---------------------------------------------------------------------------
// Launch. Inputs: 0:x_n 1:x_e 2:edge_indices 3:all_embeddings 4:W_n 5:b_n
//                 6:a 7:bias_n   (x_e, all_embeddings unused)
// ---------------------------------------------------------------------------
extern "C" void kernel_launch(void* const* d_in, const int* in_sizes, int n_in,
                              void* d_out, int out_size) {
    const float* x_n  = (const float*)d_in[0];
    const int*   edge = (const int*)  d_in[2];
    const float* W_n  = (const float*)d_in[4];
    const float* b_n  = (const float*)d_in[5];
    const float* a    = (const float*)d_in[6];
    const float* bias = (const float*)d_in[7];
    float* out = (float*)d_out;

    gemm_wx_kernel<<<(BATCH * NF) / 64, 256>>>(x_n, W_n, b_n, a);
    attn_stream_kernel<<<(BATCH * NF * 32) / 256, 256>>>(edge, bias, out);
}